// round 1
// baseline (speedup 1.0000x reference)
#include <cuda_runtime.h>
#include <math.h>

#define N_NODES 50000
#define N_EDGES 800000
#define ET      (N_EDGES + N_NODES)   // edges + self loops
#define N_G     512
#define U       64

// -------- scratch (device globals; no allocation allowed) --------
__device__ float g_h[N_NODES * U];      // h (GAT) / scaled h (GCN)
__device__ float g_x[N_NODES * U];      // current node features
__device__ float g_as[N_NODES];
__device__ float g_ad[N_NODES];
__device__ int   g_cnt[N_NODES];
__device__ int   g_rowptr[N_NODES + 1];
__device__ int   g_fill[N_NODES];
__device__ int   g_col[ET];
__device__ float g_gsum[2 * N_G];
__device__ float g_gcnt[2 * N_G];

// ---------------- utility kernels ----------------
__global__ void k_zero_cnt() {
    int i = blockIdx.x * blockDim.x + threadIdx.x;
    if (i < N_NODES) g_cnt[i] = 0;
}

__global__ void k_zero_g() {
    int i = threadIdx.x;
    if (i < 2 * N_G) { g_gsum[i] = 0.f; g_gcnt[i] = 0.f; }
}

__global__ void k_count(const int* __restrict__ ei) {
    int i = blockIdx.x * blockDim.x + threadIdx.x;
    if (i >= ET) return;
    int d = (i < N_EDGES) ? ei[N_EDGES + i] : (i - N_EDGES);
    atomicAdd(&g_cnt[d], 1);
}

// single-block exclusive scan of g_cnt -> g_rowptr/g_fill
__global__ void k_scan() {
    __shared__ int swt[32];
    __shared__ int swe[33];
    __shared__ int s_carry;
    int lane = threadIdx.x & 31, wid = threadIdx.x >> 5;
    if (threadIdx.x == 0) s_carry = 0;
    __syncthreads();
    for (int base = 0; base < N_NODES; base += 1024) {
        int i = base + threadIdx.x;
        int v = (i < N_NODES) ? g_cnt[i] : 0;
        int incl = v;
#pragma unroll
        for (int off = 1; off < 32; off <<= 1) {
            int t = __shfl_up_sync(0xffffffffu, incl, off);
            if (lane >= off) incl += t;
        }
        if (lane == 31) swt[wid] = incl;
        __syncthreads();
        if (wid == 0) {
            int wv = swt[lane];
            int winc = wv;
#pragma unroll
            for (int off = 1; off < 32; off <<= 1) {
                int t = __shfl_up_sync(0xffffffffu, winc, off);
                if (lane >= off) winc += t;
            }
            swe[lane] = winc - wv;
            if (lane == 31) swe[32] = winc;
        }
        __syncthreads();
        int excl = s_carry + swe[wid] + incl - v;
        if (i < N_NODES) { g_rowptr[i] = excl; g_fill[i] = excl; }
        __syncthreads();
        if (threadIdx.x == 0) s_carry += swe[32];
        __syncthreads();
    }
    if (threadIdx.x == 0) g_rowptr[N_NODES] = s_carry;
}

__global__ void k_scatter(const int* __restrict__ ei) {
    int i = blockIdx.x * blockDim.x + threadIdx.x;
    if (i >= ET) return;
    int s, d;
    if (i < N_EDGES) { s = ei[i]; d = ei[N_EDGES + i]; }
    else             { s = d = i - N_EDGES; }
    int pos = atomicAdd(&g_fill[d], 1);
    g_col[pos] = s;
}

// ---------------- GAT input transform: h = x@W, alpha_s, alpha_d ----------------
__global__ void k_gat_in(const float* __restrict__ x, const float* __restrict__ Wg,
                         const float* __restrict__ asrc, const float* __restrict__ adst) {
    __shared__ float Ws[9 * 64];
    __shared__ float av[128];
    for (int i = threadIdx.x; i < 9 * 64; i += blockDim.x) Ws[i] = Wg[i];
    if (threadIdx.x < 64) { av[threadIdx.x] = asrc[threadIdx.x]; av[64 + threadIdx.x] = adst[threadIdx.x]; }
    __syncthreads();
    int lane = threadIdx.x & 31;
    int wpb = blockDim.x >> 5;
    int gw = blockIdx.x * wpb + (threadIdx.x >> 5);
    int nw = gridDim.x * wpb;
    for (int n = gw; n < N_NODES; n += nw) {
        float xv = (lane < 9) ? x[n * 9 + lane] : 0.f;
        float h0 = 0.f, h1 = 0.f;
#pragma unroll
        for (int k = 0; k < 9; k++) {
            float xk = __shfl_sync(0xffffffffu, xv, k);
            h0 += xk * Ws[k * 64 + 2 * lane];
            h1 += xk * Ws[k * 64 + 2 * lane + 1];
        }
        g_h[n * 64 + 2 * lane]     = h0;
        g_h[n * 64 + 2 * lane + 1] = h1;
        float p = h0 * av[2 * lane] + h1 * av[2 * lane + 1];
        float q = h0 * av[64 + 2 * lane] + h1 * av[64 + 2 * lane + 1];
#pragma unroll
        for (int o = 16; o; o >>= 1) {
            p += __shfl_xor_sync(0xffffffffu, p, o);
            q += __shfl_xor_sync(0xffffffffu, q, o);
        }
        if (lane == 0) { g_as[n] = p; g_ad[n] = q; }
    }
}

__device__ __forceinline__ float lrelu(float v) { return v >= 0.f ? v : 0.2f * v; }

// ---------------- GAT aggregation: warp per dst node ----------------
__global__ void k_gat_agg(const float* __restrict__ bgat) {
    int warp = (blockIdx.x * blockDim.x + threadIdx.x) >> 5;
    int lane = threadIdx.x & 31;
    if (warp >= N_NODES) return;
    int r0 = g_rowptr[warp], r1 = g_rowptr[warp + 1];
    float adn = g_ad[warp];
    // pass 1: max
    float m = -INFINITY;
    for (int e = r0 + lane; e < r1; e += 32) {
        float ev = lrelu(g_as[g_col[e]] + adn);
        m = fmaxf(m, ev);
    }
#pragma unroll
    for (int o = 16; o; o >>= 1) m = fmaxf(m, __shfl_xor_sync(0xffffffffu, m, o));
    // pass 2: denom
    float dsum = 0.f;
    for (int e = r0 + lane; e < r1; e += 32) {
        float ev = lrelu(g_as[g_col[e]] + adn);
        dsum += expf(ev - m);
    }
#pragma unroll
    for (int o = 16; o; o >>= 1) dsum += __shfl_xor_sync(0xffffffffu, dsum, o);
    float inv = 1.f / dsum;
    // pass 3: weighted sum of h[src]
    float ax = 0.f, ay = 0.f;
    for (int base = r0; base < r1; base += 32) {
        int e = base + lane;
        int s = 0; float c = 0.f;
        if (e < r1) {
            s = g_col[e];
            c = expf(lrelu(g_as[s] + adn) - m) * inv;
        }
        int cnt = min(32, r1 - base);
        for (int j = 0; j < cnt; j++) {
            int   sb = __shfl_sync(0xffffffffu, s, j);
            float cb = __shfl_sync(0xffffffffu, c, j);
            float2 hv = *(const float2*)&g_h[sb * 64 + 2 * lane];
            ax += cb * hv.x; ay += cb * hv.y;
        }
    }
    g_x[warp * 64 + 2 * lane]     = tanhf(ax + bgat[2 * lane]);
    g_x[warp * 64 + 2 * lane + 1] = tanhf(ay + bgat[2 * lane + 1]);
}

// ---------------- GCN: h_scaled = (x@W)*dinv ----------------
__global__ void k_gemm_scale(const float* __restrict__ W) {
    __shared__ float Ws[64 * 64];
    __shared__ float xr[8][64];
    for (int i = threadIdx.x; i < 64 * 64; i += blockDim.x) Ws[i] = W[i];
    __syncthreads();
    int lane = threadIdx.x & 31, wid = threadIdx.x >> 5;
    int wpb = blockDim.x >> 5;
    int gw = blockIdx.x * wpb + wid;
    int nw = gridDim.x * wpb;
    for (int n = gw; n < N_NODES; n += nw) {
        xr[wid][lane]      = g_x[n * 64 + lane];
        xr[wid][lane + 32] = g_x[n * 64 + 32 + lane];
        __syncwarp();
        float a0 = 0.f, a1 = 0.f;
#pragma unroll 16
        for (int k = 0; k < 64; k++) {
            float xk = xr[wid][k];
            float2 w = *(const float2*)&Ws[k * 64 + 2 * lane];
            a0 += xk * w.x; a1 += xk * w.y;
        }
        float dinv = rsqrtf((float)(g_rowptr[n + 1] - g_rowptr[n]));
        g_h[n * 64 + 2 * lane]     = a0 * dinv;
        g_h[n * 64 + 2 * lane + 1] = a1 * dinv;
        __syncwarp();
    }
}

// ---------------- GCN aggregation: warp per dst node ----------------
__global__ void k_gcn_agg(const float* __restrict__ bg) {
    int warp = (blockIdx.x * blockDim.x + threadIdx.x) >> 5;
    int lane = threadIdx.x & 31;
    if (warp >= N_NODES) return;
    int r0 = g_rowptr[warp], r1 = g_rowptr[warp + 1];
    float ax = 0.f, ay = 0.f;
    for (int base = r0; base < r1; base += 32) {
        int e = base + lane;
        int s = (e < r1) ? g_col[e] : 0;
        int cnt = min(32, r1 - base);
        for (int j = 0; j < cnt; j++) {
            int sb = __shfl_sync(0xffffffffu, s, j);
            float2 hv = *(const float2*)&g_h[sb * 64 + 2 * lane];
            ax += hv.x; ay += hv.y;
        }
    }
    float dinv = rsqrtf((float)(r1 - r0));
    g_x[warp * 64 + 2 * lane]     = tanhf(dinv * ax + bg[2 * lane]);
    g_x[warp * 64 + 2 * lane + 1] = tanhf(dinv * ay + bg[2 * lane + 1]);
}

// ---------------- MLP + graph pooling ----------------
__global__ void k_mlp_pool(const float* __restrict__ W1, const float* __restrict__ b1,
                           const float* __restrict__ W2, const float* __restrict__ b2,
                           const float* __restrict__ W3, const float* __restrict__ b3,
                           const int* __restrict__ batch, int br) {
    __shared__ float W1s[64 * 64];
    __shared__ float W2s[64 * 32];
    __shared__ float W3s[32];
    __shared__ float b1s[64];
    __shared__ float b2s[32];
    __shared__ float xr[8][64];
    __shared__ float y1s[8][64];
    for (int i = threadIdx.x; i < 64 * 64; i += blockDim.x) W1s[i] = W1[i];
    for (int i = threadIdx.x; i < 64 * 32; i += blockDim.x) W2s[i] = W2[i];
    if (threadIdx.x < 64) b1s[threadIdx.x] = b1[threadIdx.x];
    if (threadIdx.x < 32) { W3s[threadIdx.x] = W3[threadIdx.x]; b2s[threadIdx.x] = b2[threadIdx.x]; }
    __syncthreads();
    float b3v = b3[0];
    int lane = threadIdx.x & 31, wid = threadIdx.x >> 5;
    int wpb = blockDim.x >> 5;
    int gw = blockIdx.x * wpb + wid;
    int nw = gridDim.x * wpb;
    for (int n = gw; n < N_NODES; n += nw) {
        xr[wid][lane]      = g_x[n * 64 + lane];
        xr[wid][lane + 32] = g_x[n * 64 + 32 + lane];
        __syncwarp();
        float t0 = b1s[2 * lane], t1 = b1s[2 * lane + 1];
#pragma unroll 16
        for (int k = 0; k < 64; k++) {
            float xk = xr[wid][k];
            float2 w = *(const float2*)&W1s[k * 64 + 2 * lane];
            t0 += xk * w.x; t1 += xk * w.y;
        }
        y1s[wid][2 * lane]     = tanhf(t0);
        y1s[wid][2 * lane + 1] = tanhf(t1);
        __syncwarp();
        float t = b2s[lane];
#pragma unroll 16
        for (int k = 0; k < 64; k++) t += y1s[wid][k] * W2s[k * 32 + lane];
        float y3 = tanhf(t) * W3s[lane];
#pragma unroll
        for (int o = 16; o; o >>= 1) y3 += __shfl_xor_sync(0xffffffffu, y3, o);
        if (lane == 0) {
            y3 += b3v;
            int g = batch[n];
            atomicAdd(&g_gsum[br * N_G + g], y3);
            atomicAdd(&g_gcnt[br * N_G + g], 1.0f);
        }
        __syncwarp();
    }
}

__global__ void k_final(float* __restrict__ out) {
    int g = blockIdx.x * blockDim.x + threadIdx.x;
    if (g >= N_G) return;
    float ua = g_gsum[g]         / fmaxf(g_gcnt[g], 1.f);
    float ub = g_gsum[N_G + g]   / fmaxf(g_gcnt[N_G + g], 1.f);
    out[g] = 1.f / (1.f + expf(-(ub - ua)));
}

// ---------------- launch ----------------
extern "C" void kernel_launch(void* const* d_in, const int* in_sizes, int n_in,
                              void* d_out, int out_size) {
    const float* x[2]   = { (const float*)d_in[0], (const float*)d_in[1] };
    const int*   ei[2]  = { (const int*)d_in[2],   (const int*)d_in[3]   };
    const int*   bat[2] = { (const int*)d_in[4],   (const int*)d_in[5]   };
    const float* Wgat = (const float*)d_in[6];
    const float* asrc = (const float*)d_in[7];
    const float* adst = (const float*)d_in[8];
    const float* bgat = (const float*)d_in[9];
    const float* Wgcn = (const float*)d_in[10];  // [2,64,64]
    const float* bgcn = (const float*)d_in[11];  // [2,64]
    const float* W1 = (const float*)d_in[12];
    const float* b1 = (const float*)d_in[13];
    const float* W2 = (const float*)d_in[14];
    const float* b2 = (const float*)d_in[15];
    const float* W3 = (const float*)d_in[16];
    const float* b3 = (const float*)d_in[17];
    float* out = (float*)d_out;

    k_zero_g<<<1, 1024>>>();
    for (int br = 0; br < 2; br++) {
        k_zero_cnt<<<(N_NODES + 1023) / 1024, 1024>>>();
        k_count<<<(ET + 255) / 256, 256>>>(ei[br]);
        k_scan<<<1, 1024>>>();
        k_scatter<<<(ET + 255) / 256, 256>>>(ei[br]);
        k_gat_in<<<592, 256>>>(x[br], Wgat, asrc, adst);
        k_gat_agg<<<(N_NODES + 7) / 8, 256>>>(bgat);
        for (int l = 0; l < 2; l++) {
            k_gemm_scale<<<592, 256>>>(Wgcn + l * 64 * 64);
            k_gcn_agg<<<(N_NODES + 7) / 8, 256>>>(bgcn + l * 64);
        }
        k_mlp_pool<<<592, 256>>>(W1, b1, W2, b2, W3, b3, bat[br], br);
    }
    k_final<<<2, 256>>>(out);
}

// round 3
// speedup vs baseline: 1.5111x; 1.5111x over previous
#include <cuda_runtime.h>
#include <math.h>

#define N_NODES 50000
#define N_EDGES 800000
#define ET      (N_EDGES + N_NODES)
#define ET2     (2 * ET)
#define NB      (2 * N_NODES)
#define N_G     512
#define NBLK    ((NB + 1023) / 1024)

// -------- scratch (device globals; no allocation allowed) --------
__device__ float g_h[NB * 64];
__device__ float g_x[NB * 64];
__device__ float g_as[NB];
__device__ float g_ad[NB];
__device__ int   g_cnt[NB];
__device__ int   g_rowptr[NB + 1];
__device__ int   g_fill[NB];
__device__ int   g_col[ET2];
__device__ int   g_bsum[NBLK];
__device__ int   g_boff[NBLK];
__device__ float g_gstats[4 * N_G];   // [0,2G): sums  [2G,4G): counts

__device__ __forceinline__ float lrelu(float v) { return v >= 0.f ? v : 0.2f * v; }
// buffer selector: 0 -> g_x, 1 -> g_h  (device symbols must NOT be passed from host!)
__device__ __forceinline__ float* bufsel(int s) { return s ? g_h : g_x; }

// ---------------- zero ----------------
__global__ void k_zero() {
    int i = blockIdx.x * blockDim.x + threadIdx.x;
    if (i < NB) g_cnt[i] = 0;
    if (i < 4 * N_G) g_gstats[i] = 0.f;
}

// ---------------- degree count over both branches ----------------
__global__ void k_count(const int* __restrict__ eA, const int* __restrict__ eB) {
    int i = blockIdx.x * blockDim.x + threadIdx.x;
    if (i >= ET2) return;
    int br = (i >= ET) ? 1 : 0;
    int j = i - br * ET;
    const int* ei = br ? eB : eA;
    int d = (j < N_EDGES) ? ei[N_EDGES + j] : (j - N_EDGES);
    atomicAdd(&g_cnt[br * N_NODES + d], 1);
}

// ---------------- hierarchical scan ----------------
__global__ void k_scan1() {   // per-block (1024) exclusive scan + block sums
    __shared__ int swt[32];
    int i = blockIdx.x * 1024 + threadIdx.x;
    int lane = threadIdx.x & 31, wid = threadIdx.x >> 5;
    int v = (i < NB) ? g_cnt[i] : 0;
    int incl = v;
#pragma unroll
    for (int off = 1; off < 32; off <<= 1) {
        int t = __shfl_up_sync(0xffffffffu, incl, off);
        if (lane >= off) incl += t;
    }
    if (lane == 31) swt[wid] = incl;
    __syncthreads();
    if (wid == 0) {
        int wv = swt[lane];
        int winc = wv;
#pragma unroll
        for (int off = 1; off < 32; off <<= 1) {
            int t = __shfl_up_sync(0xffffffffu, winc, off);
            if (lane >= off) winc += t;
        }
        swt[lane] = winc - wv;
    }
    __syncthreads();
    int excl = swt[wid] + incl - v;
    if (i < NB) g_rowptr[i] = excl;
    if (threadIdx.x == 1023) g_bsum[blockIdx.x] = excl + v;
}

__global__ void k_scan2() {   // 1 block, 128 threads scans NBLK block sums
    __shared__ int swt[4];
    int t = threadIdx.x;
    int lane = t & 31, wid = t >> 5;
    int v = (t < NBLK) ? g_bsum[t] : 0;
    int incl = v;
#pragma unroll
    for (int off = 1; off < 32; off <<= 1) {
        int tt = __shfl_up_sync(0xffffffffu, incl, off);
        if (lane >= off) incl += tt;
    }
    if (lane == 31) swt[wid] = incl;
    __syncthreads();
    int base = 0;
    for (int w = 0; w < wid; w++) base += swt[w];
    int excl = base + incl - v;
    if (t < NBLK) g_boff[t] = excl;
    if (t == 127) g_rowptr[NB] = base + incl;
}

__global__ void k_scan3() {   // add block offsets, produce fill
    int i = blockIdx.x * 1024 + threadIdx.x;
    if (i < NB) {
        int r = g_rowptr[i] + g_boff[blockIdx.x];
        g_rowptr[i] = r;
        g_fill[i] = r;
    }
}

// ---------------- scatter into CSR ----------------
__global__ void k_scatter(const int* __restrict__ eA, const int* __restrict__ eB) {
    int i = blockIdx.x * blockDim.x + threadIdx.x;
    if (i >= ET2) return;
    int br = (i >= ET) ? 1 : 0;
    int j = i - br * ET;
    const int* ei = br ? eB : eA;
    int s, d;
    if (j < N_EDGES) { s = ei[j]; d = ei[N_EDGES + j]; }
    else             { s = d = j - N_EDGES; }
    int gd = br * N_NODES + d;
    int pos = atomicAdd(&g_fill[gd], 1);
    g_col[pos] = br * N_NODES + s;
}

// ---------------- GAT input transform ----------------
__global__ void k_gat_in(const float* __restrict__ xA, const float* __restrict__ xB,
                         const float* __restrict__ Wg,
                         const float* __restrict__ asrc, const float* __restrict__ adst) {
    __shared__ float Ws[9 * 64];
    __shared__ float av[128];
    for (int i = threadIdx.x; i < 9 * 64; i += blockDim.x) Ws[i] = Wg[i];
    if (threadIdx.x < 64) { av[threadIdx.x] = asrc[threadIdx.x]; av[64 + threadIdx.x] = adst[threadIdx.x]; }
    __syncthreads();
    int lane = threadIdx.x & 31;
    int wpb = blockDim.x >> 5;
    int gw = blockIdx.x * wpb + (threadIdx.x >> 5);
    int nw = gridDim.x * wpb;
    for (int n = gw; n < NB; n += nw) {
        const float* x = (n < N_NODES) ? xA : xB;
        int local = (n < N_NODES) ? n : n - N_NODES;
        float xv = (lane < 9) ? x[local * 9 + lane] : 0.f;
        float h0 = 0.f, h1 = 0.f;
#pragma unroll
        for (int k = 0; k < 9; k++) {
            float xk = __shfl_sync(0xffffffffu, xv, k);
            h0 += xk * Ws[k * 64 + 2 * lane];
            h1 += xk * Ws[k * 64 + 2 * lane + 1];
        }
        g_h[n * 64 + 2 * lane]     = h0;
        g_h[n * 64 + 2 * lane + 1] = h1;
        float p = h0 * av[2 * lane] + h1 * av[2 * lane + 1];
        float q = h0 * av[64 + 2 * lane] + h1 * av[64 + 2 * lane + 1];
#pragma unroll
        for (int o = 16; o; o >>= 1) {
            p += __shfl_xor_sync(0xffffffffu, p, o);
            q += __shfl_xor_sync(0xffffffffu, q, o);
        }
        if (lane == 0) { g_as[n] = p; g_ad[n] = q; }
    }
}

// ---------------- GAT aggregation (online softmax, warp per dst) ----------------
__global__ void k_gat_agg(const float* __restrict__ bgat) {
    int node = (blockIdx.x * blockDim.x + threadIdx.x) >> 5;
    int lane = threadIdx.x & 31;
    if (node >= NB) return;
    int r0 = g_rowptr[node], r1 = g_rowptr[node + 1];
    float adn = g_ad[node];
    float m = -1e30f, s = 0.f;
    for (int e = r0 + lane; e < r1; e += 32) {
        float ev = lrelu(g_as[g_col[e]] + adn);
        if (ev > m) { s = s * expf(m - ev) + 1.f; m = ev; }
        else         s += expf(ev - m);
    }
#pragma unroll
    for (int o = 16; o; o >>= 1) {
        float m2 = __shfl_xor_sync(0xffffffffu, m, o);
        float s2 = __shfl_xor_sync(0xffffffffu, s, o);
        float M = fmaxf(m, m2);
        s = s * expf(m - M) + s2 * expf(m2 - M);
        m = M;
    }
    float inv = 1.f / s;
    float ax = 0.f, ay = 0.f;
    for (int base = r0; base < r1; base += 32) {
        int e = base + lane;
        int sc = 0; float c = 0.f;
        if (e < r1) {
            sc = g_col[e];
            c = expf(lrelu(g_as[sc] + adn) - m) * inv;
        }
        int cnt = min(32, r1 - base);
        for (int j = 0; j < cnt; j++) {
            int   sb = __shfl_sync(0xffffffffu, sc, j);
            float cb = __shfl_sync(0xffffffffu, c, j);
            float2 hv = *(const float2*)&g_h[sb * 64 + 2 * lane];
            ax += cb * hv.x; ay += cb * hv.y;
        }
    }
    g_x[node * 64 + 2 * lane]     = tanhf(ax + bgat[2 * lane]);
    g_x[node * 64 + 2 * lane + 1] = tanhf(ay + bgat[2 * lane + 1]);
}

// ---------------- tiled 64x64x64 GEMM over device buffers (selector args) ----------------
// mode 0: Y = (X@W) * dinv(row)      mode 1: Y = tanh(X@W + bias)
__global__ void k_gemm64(int xsel, int ysel, const float* __restrict__ W,
                         const float* __restrict__ bias, int mode) {
    __shared__ float xs[64][68];
    __shared__ float ws[64][68];
    const float* X = bufsel(xsel);
    float*       Y = bufsel(ysel);
    int n0 = blockIdx.x * 64;
    int t = threadIdx.x;
    for (int i = t; i < 64 * 16; i += 256) {
        int k = i >> 4, c = (i & 15) << 2;
        *(float4*)&ws[k][c] = *(const float4*)&W[k * 64 + c];
    }
    for (int i = t; i < 64 * 16; i += 256) {
        int node = i & 63, kc = i >> 6;
        int n = n0 + node;
        float4 xv = make_float4(0.f, 0.f, 0.f, 0.f);
        if (n < NB) xv = *(const float4*)&X[n * 64 + (kc << 2)];
        xs[(kc << 2) + 0][node] = xv.x;
        xs[(kc << 2) + 1][node] = xv.y;
        xs[(kc << 2) + 2][node] = xv.z;
        xs[(kc << 2) + 3][node] = xv.w;
    }
    __syncthreads();
    int tx = t & 15, ty = t >> 4;
    float acc[4][4] = {};
#pragma unroll 8
    for (int k = 0; k < 64; k++) {
        float4 a = *(const float4*)&xs[k][tx << 2];
        float4 b = *(const float4*)&ws[k][ty << 2];
        acc[0][0] += a.x * b.x; acc[0][1] += a.x * b.y; acc[0][2] += a.x * b.z; acc[0][3] += a.x * b.w;
        acc[1][0] += a.y * b.x; acc[1][1] += a.y * b.y; acc[1][2] += a.y * b.z; acc[1][3] += a.y * b.w;
        acc[2][0] += a.z * b.x; acc[2][1] += a.z * b.y; acc[2][2] += a.z * b.z; acc[2][3] += a.z * b.w;
        acc[3][0] += a.w * b.x; acc[3][1] += a.w * b.y; acc[3][2] += a.w * b.z; acc[3][3] += a.w * b.w;
    }
    float4 bs = make_float4(0.f, 0.f, 0.f, 0.f);
    if (mode == 1) bs = *(const float4*)&bias[ty << 2];
#pragma unroll
    for (int i = 0; i < 4; i++) {
        int n = n0 + (tx << 2) + i;
        if (n >= NB) break;
        float4 r;
        if (mode == 0) {
            float dinv = rsqrtf((float)(g_rowptr[n + 1] - g_rowptr[n]));
            r = make_float4(acc[i][0] * dinv, acc[i][1] * dinv, acc[i][2] * dinv, acc[i][3] * dinv);
        } else {
            r = make_float4(tanhf(acc[i][0] + bs.x), tanhf(acc[i][1] + bs.y),
                            tanhf(acc[i][2] + bs.z), tanhf(acc[i][3] + bs.w));
        }
        *(float4*)&Y[n * 64 + (ty << 2)] = r;
    }
}

// ---------------- GCN aggregation ----------------
__global__ void k_gcn_agg(const float* __restrict__ bg) {
    int node = (blockIdx.x * blockDim.x + threadIdx.x) >> 5;
    int lane = threadIdx.x & 31;
    if (node >= NB) return;
    int r0 = g_rowptr[node], r1 = g_rowptr[node + 1];
    float ax = 0.f, ay = 0.f;
    for (int base = r0; base < r1; base += 32) {
        int e = base + lane;
        int s = (e < r1) ? g_col[e] : 0;
        int cnt = min(32, r1 - base);
        for (int j = 0; j < cnt; j++) {
            int sb = __shfl_sync(0xffffffffu, s, j);
            float2 hv = *(const float2*)&g_h[sb * 64 + 2 * lane];
            ax += hv.x; ay += hv.y;
        }
    }
    float dinv = rsqrtf((float)(r1 - r0));
    g_x[node * 64 + 2 * lane]     = tanhf(dinv * ax + bg[2 * lane]);
    g_x[node * 64 + 2 * lane + 1] = tanhf(dinv * ay + bg[2 * lane + 1]);
}

// ---------------- MLP layers 2,3 + pooling (reads y1 = g_h) ----------------
__global__ void k_mlp23_pool(const float* __restrict__ W2, const float* __restrict__ b2,
                             const float* __restrict__ W3, const float* __restrict__ b3,
                             const int* __restrict__ batA, const int* __restrict__ batB) {
    __shared__ float W2s[64 * 32];
    __shared__ float W3s[32];
    __shared__ float b2s[32];
    __shared__ float xr[8][64];
    for (int i = threadIdx.x; i < 64 * 32; i += blockDim.x) W2s[i] = W2[i];
    if (threadIdx.x < 32) { W3s[threadIdx.x] = W3[threadIdx.x]; b2s[threadIdx.x] = b2[threadIdx.x]; }
    __syncthreads();
    float b3v = b3[0];
    int lane = threadIdx.x & 31, wid = threadIdx.x >> 5;
    int wpb = blockDim.x >> 5;
    int gw = blockIdx.x * wpb + wid;
    int nw = gridDim.x * wpb;
    for (int n = gw; n < NB; n += nw) {
        xr[wid][lane]      = g_h[n * 64 + lane];
        xr[wid][lane + 32] = g_h[n * 64 + 32 + lane];
        __syncwarp();
        float tacc = b2s[lane];
#pragma unroll 16
        for (int k = 0; k < 64; k++) tacc += xr[wid][k] * W2s[k * 32 + lane];
        float y3 = tanhf(tacc) * W3s[lane];
#pragma unroll
        for (int o = 16; o; o >>= 1) y3 += __shfl_xor_sync(0xffffffffu, y3, o);
        if (lane == 0) {
            y3 += b3v;
            int br = (n < N_NODES) ? 0 : 1;
            int local = n - br * N_NODES;
            int g = br ? batB[local] : batA[local];
            atomicAdd(&g_gstats[br * N_G + g], y3);
            atomicAdd(&g_gstats[2 * N_G + br * N_G + g], 1.0f);
        }
        __syncwarp();
    }
}

__global__ void k_final(float* __restrict__ out) {
    int g = blockIdx.x * blockDim.x + threadIdx.x;
    if (g >= N_G) return;
    float ua = g_gstats[g]       / fmaxf(g_gstats[2 * N_G + g], 1.f);
    float ub = g_gstats[N_G + g] / fmaxf(g_gstats[3 * N_G + g], 1.f);
    out[g] = 1.f / (1.f + expf(-(ub - ua)));
}

// ---------------- launch ----------------
extern "C" void kernel_launch(void* const* d_in, const int* in_sizes, int n_in,
                              void* d_out, int out_size) {
    const float* xA   = (const float*)d_in[0];
    const float* xB   = (const float*)d_in[1];
    const int*   eA   = (const int*)d_in[2];
    const int*   eB   = (const int*)d_in[3];
    const int*   batA = (const int*)d_in[4];
    const int*   batB = (const int*)d_in[5];
    const float* Wgat = (const float*)d_in[6];
    const float* asrc = (const float*)d_in[7];
    const float* adst = (const float*)d_in[8];
    const float* bgat = (const float*)d_in[9];
    const float* Wgcn = (const float*)d_in[10];
    const float* bgcn = (const float*)d_in[11];
    const float* W1 = (const float*)d_in[12];
    const float* b1 = (const float*)d_in[13];
    const float* W2 = (const float*)d_in[14];
    const float* b2 = (const float*)d_in[15];
    const float* W3 = (const float*)d_in[16];
    const float* b3 = (const float*)d_in[17];
    float* out = (float*)d_out;

    const int AGG_BLOCKS = (NB * 32 + 255) / 256;
    const int GEMM_BLOCKS = (NB + 63) / 64;

    k_zero<<<(NB + 255) / 256, 256>>>();
    k_count<<<(ET2 + 255) / 256, 256>>>(eA, eB);
    k_scan1<<<NBLK, 1024>>>();
    k_scan2<<<1, 128>>>();
    k_scan3<<<NBLK, 1024>>>();
    k_scatter<<<(ET2 + 255) / 256, 256>>>(eA, eB);
    k_gat_in<<<1184, 256>>>(xA, xB, Wgat, asrc, adst);
    k_gat_agg<<<AGG_BLOCKS, 256>>>(bgat);
    for (int l = 0; l < 2; l++) {
        k_gemm64<<<GEMM_BLOCKS, 256>>>(0, 1, Wgcn + l * 64 * 64, nullptr, 0);  // g_x -> g_h
        k_gcn_agg<<<AGG_BLOCKS, 256>>>(bgcn + l * 64);                          // g_h -> g_x
    }
    k_gemm64<<<GEMM_BLOCKS, 256>>>(0, 1, W1, b1, 1);                            // g_x -> g_h
    k_mlp23_pool<<<1184, 256>>>(W2, b2, W3, b3, batA, batB);
    k_final<<<2, 256>>>(out);
}